// round 1
// baseline (speedup 1.0000x reference)
#include <cuda_runtime.h>

// Problem constants (fixed shapes for this problem)
#define TT 4096      // tokens = B*S = 2*2048
#define HH 2048      // hidden
#define DD 2048      // intermediate (gate_up is 2*DD)
#define EE 16        // experts
#define KTOP 4       // top-k
#define ALPHA_C 1.702f
#define LIMIT_C 7.0f

// ---------------- device scratch (static; no runtime allocation) ----------
__device__ int   g_cnt[EE];
__device__ int   g_rows[EE * TT];            // token index per (expert, slot)
__device__ float g_wt[EE * TT];              // combine weight per (expert, slot)
__device__ float g_gated[(size_t)EE * TT * DD];  // 537 MB activation scratch

// ---------------- zero output + counters ----------------------------------
__global__ void zero_kernel(float* __restrict__ y) {
    size_t i = (size_t)blockIdx.x * blockDim.x + threadIdx.x;
    size_t n4 = (size_t)TT * HH / 4;
    if (i < n4) {
        float4 z = {0.f, 0.f, 0.f, 0.f};
        reinterpret_cast<float4*>(y)[i] = z;
    }
    if (blockIdx.x == 0 && threadIdx.x < EE) g_cnt[threadIdx.x] = 0;
}

// ---------------- router: logits -> top4 -> softmax -> expert lists -------
__global__ void __launch_bounds__(512) router_kernel(
    const float* __restrict__ x, const float* __restrict__ wr,
    const float* __restrict__ br, float* __restrict__ scores) {
    int t = blockIdx.x;
    int lane = threadIdx.x & 31;
    int e = threadIdx.x >> 5;     // 16 warps -> 16 experts

    const float* xr = x + (size_t)t * HH;
    const float* w  = wr + (size_t)e * HH;
    float s = 0.f;
    for (int i = lane; i < HH; i += 32) s += xr[i] * w[i];
    #pragma unroll
    for (int o = 16; o > 0; o >>= 1) s += __shfl_xor_sync(0xffffffffu, s, o);

    __shared__ float logit[EE];
    if (lane == 0) logit[e] = s + br[e];
    __syncthreads();

    if (threadIdx.x == 0) {
        float v[EE];
        #pragma unroll
        for (int i = 0; i < EE; i++) v[i] = logit[i];
        int bi[KTOP]; float bv[KTOP];
        #pragma unroll
        for (int k = 0; k < KTOP; k++) {
            float best = -1e30f; int b = 0;
            #pragma unroll
            for (int i = 0; i < EE; i++)
                if (v[i] > best) { best = v[i]; b = i; }   // strict > : lowest idx on ties
            bv[k] = best; bi[k] = b; v[b] = -1e30f;
        }
        float m = bv[0];
        float ex[KTOP], sum = 0.f;
        #pragma unroll
        for (int k = 0; k < KTOP; k++) { ex[k] = __expf(bv[k] - m); sum += ex[k]; }
        float inv = 1.f / sum;
        #pragma unroll
        for (int k = 0; k < KTOP; k++) {
            float sc = ex[k] * inv;           // softmax value
            if (scores) scores[t * KTOP + k] = sc * 0.25f;   // reference scores = softmax/TOP_K
            int pos = atomicAdd(&g_cnt[bi[k]], 1);
            g_rows[bi[k] * TT + pos] = t;
            g_wt[bi[k] * TT + pos]  = sc;     // (softmax/4)*4 cancels
        }
    }
}

// ---------------- GEMM1: gathered x @ Wgu -> GLU activation ---------------
// 64 rows x 64 "d" columns per block, but computes BOTH gate col n and up
// col n+DD so the activation fuses in-register.
__global__ void __launch_bounds__(256) gemm1_kernel(
    const float* __restrict__ x, const float* __restrict__ wgu,
    const float* __restrict__ bgu) {
    int e = blockIdx.z;
    int cnt = g_cnt[e];
    int m0 = blockIdx.y * 64;
    if (m0 >= cnt) return;
    int n0 = blockIdx.x * 64;            // in [0, DD)

    __shared__ float As[64][17];
    __shared__ float Bg[16][64];
    __shared__ float Bu[16][64];
    __shared__ int   tok[64];

    int tid = threadIdx.x;
    if (tid < 64) {
        int r = m0 + tid;
        tok[tid] = (r < cnt) ? g_rows[e * TT + r] : -1;
    }
    __syncthreads();

    int tx = tid & 15, ty = tid >> 4;
    float ag[4][4] = {}, au[4][4] = {};

    const float* Bbase = wgu + (size_t)e * HH * (2 * DD);
    int ar = tid >> 2;            // A row handled by this thread
    int ak = (tid & 3) * 4;       // 4 consecutive k's
    int tkn = tok[ar];
    const float* arow = (tkn >= 0) ? (x + (size_t)tkn * HH) : nullptr;

    for (int k0 = 0; k0 < HH; k0 += 16) {
        float4 a4 = {0.f, 0.f, 0.f, 0.f};
        if (arow) a4 = *reinterpret_cast<const float4*>(arow + k0 + ak);
        As[ar][ak + 0] = a4.x; As[ar][ak + 1] = a4.y;
        As[ar][ak + 2] = a4.z; As[ar][ak + 3] = a4.w;
        #pragma unroll
        for (int i = 0; i < 4; i++) {
            int idx = tid + i * 256;
            int kk = idx >> 6, n = idx & 63;
            const float* bp = Bbase + (size_t)(k0 + kk) * (2 * DD) + n0 + n;
            Bg[kk][n] = bp[0];
            Bu[kk][n] = bp[DD];
        }
        __syncthreads();
        #pragma unroll
        for (int kk = 0; kk < 16; kk++) {
            float a[4], bg[4], bu[4];
            #pragma unroll
            for (int i = 0; i < 4; i++) a[i] = As[ty * 4 + i][kk];
            #pragma unroll
            for (int j = 0; j < 4; j++) { bg[j] = Bg[kk][tx * 4 + j]; bu[j] = Bu[kk][tx * 4 + j]; }
            #pragma unroll
            for (int i = 0; i < 4; i++)
                #pragma unroll
                for (int j = 0; j < 4; j++) {
                    ag[i][j] += a[i] * bg[j];
                    au[i][j] += a[i] * bu[j];
                }
        }
        __syncthreads();
    }

    const float* bgp = bgu + (size_t)e * (2 * DD);
    #pragma unroll
    for (int i = 0; i < 4; i++) {
        int r = ty * 4 + i;
        float* orow = g_gated + ((size_t)e * TT + m0 + r) * DD + n0;
        #pragma unroll
        for (int j = 0; j < 4; j++) {
            int n = n0 + tx * 4 + j;
            float gate = ag[i][j] + bgp[n];
            float up   = au[i][j] + bgp[DD + n];
            gate = fminf(gate, LIMIT_C);
            up   = fminf(fmaxf(up, -LIMIT_C), LIMIT_C);
            float glu = gate / (1.f + __expf(-ALPHA_C * gate));
            orow[tx * 4 + j] = (up + 1.f) * glu;
        }
    }
}

// ---------------- GEMM2: gated @ Wd, weighted scatter-add into y ----------
__global__ void __launch_bounds__(256) gemm2_kernel(
    const float* __restrict__ dp, const float* __restrict__ bd,
    float* __restrict__ y) {
    int e = blockIdx.z;
    int cnt = g_cnt[e];
    int m0 = blockIdx.y * 64;
    if (m0 >= cnt) return;
    int n0 = blockIdx.x * 64;            // in [0, HH)

    __shared__ float As[64][17];
    __shared__ float Bs[16][64];
    __shared__ int   tok[64];
    __shared__ float wts[64];

    int tid = threadIdx.x;
    if (tid < 64) {
        int r = m0 + tid;
        if (r < cnt) { tok[tid] = g_rows[e * TT + r]; wts[tid] = g_wt[e * TT + r]; }
        else         { tok[tid] = -1; wts[tid] = 0.f; }
    }
    __syncthreads();

    int tx = tid & 15, ty = tid >> 4;
    float acc[4][4] = {};

    const float* Ab = g_gated + ((size_t)e * TT + m0) * DD;
    const float* Bb = dp + (size_t)e * DD * HH + n0;
    int ar = tid >> 2;
    int ak = (tid & 3) * 4;
    const float* arow = Ab + (size_t)ar * DD;

    for (int k0 = 0; k0 < DD; k0 += 16) {
        float4 a4 = *reinterpret_cast<const float4*>(arow + k0 + ak);
        As[ar][ak + 0] = a4.x; As[ar][ak + 1] = a4.y;
        As[ar][ak + 2] = a4.z; As[ar][ak + 3] = a4.w;
        #pragma unroll
        for (int i = 0; i < 4; i++) {
            int idx = tid + i * 256;
            int kk = idx >> 6, n = idx & 63;
            Bs[kk][n] = Bb[(size_t)(k0 + kk) * HH + n];
        }
        __syncthreads();
        #pragma unroll
        for (int kk = 0; kk < 16; kk++) {
            float a[4], b[4];
            #pragma unroll
            for (int i = 0; i < 4; i++) a[i] = As[ty * 4 + i][kk];
            #pragma unroll
            for (int j = 0; j < 4; j++) b[j] = Bs[kk][tx * 4 + j];
            #pragma unroll
            for (int i = 0; i < 4; i++)
                #pragma unroll
                for (int j = 0; j < 4; j++)
                    acc[i][j] += a[i] * b[j];
        }
        __syncthreads();
    }

    const float* bdp = bd + (size_t)e * HH;
    #pragma unroll
    for (int i = 0; i < 4; i++) {
        int r = ty * 4 + i;
        if (m0 + r < cnt) {
            float wv = wts[r];
            int t = tok[r];
            float* yrow = y + (size_t)t * HH + n0;
            #pragma unroll
            for (int j = 0; j < 4; j++) {
                int n = n0 + tx * 4 + j;
                float out = (acc[i][j] + bdp[n]) * wv;
                atomicAdd(yrow + tx * 4 + j, out);
            }
        }
    }
}

// ---------------- launch ---------------------------------------------------
extern "C" void kernel_launch(void* const* d_in, const int* in_sizes, int n_in,
                              void* d_out, int out_size) {
    const float* x   = (const float*)d_in[0];   // [T, H]
    const float* wr  = (const float*)d_in[1];   // [E, H]
    const float* br  = (const float*)d_in[2];   // [E]
    const float* wgu = (const float*)d_in[3];   // [E, H, 2D]
    const float* bgu = (const float*)d_in[4];   // [E, 2D]
    const float* dp  = (const float*)d_in[5];   // [E, D, H]
    const float* bd  = (const float*)d_in[6];   // [E, H]
    (void)in_sizes; (void)n_in;

    float* y = (float*)d_out;
    // reference returns (y, scores); write scores after y iff the buffer has room
    float* scores = nullptr;
    if ((size_t)out_size >= (size_t)TT * HH + (size_t)TT * KTOP)
        scores = y + (size_t)TT * HH;

    {
        int threads = 256;
        int blocks = (int)(((size_t)TT * HH / 4 + threads - 1) / threads);
        zero_kernel<<<blocks, threads>>>(y);
    }
    router_kernel<<<TT, 512>>>(x, wr, br, scores);

    dim3 g1(DD / 64, TT / 64, EE);
    gemm1_kernel<<<g1, 256>>>(x, wgu, bgu);

    dim3 g2(HH / 64, TT / 64, EE);
    gemm2_kernel<<<g2, 256>>>(dp, bd, y);
}

// round 2
// speedup vs baseline: 3.3899x; 3.3899x over previous
#include <cuda_runtime.h>
#include <cstdint>

// Problem constants
#define TT 4096      // tokens = B*S
#define HH 2048      // hidden
#define DD 2048      // intermediate (gate_up = 2*DD)
#define EE 16
#define KTOP 4
#define ALPHA_C 1.702f
#define LIMIT_C 7.0f

// ---------------- device scratch ----------------
__device__ int   g_cnt[EE];
__device__ int   g_rows[EE * TT];
__device__ float g_wt[EE * TT];
__device__ float g_gated[(size_t)EE * TT * DD];

__device__ __forceinline__ float to_tf32(float x) {
    float y;
    asm("cvt.rna.tf32.f32 %0, %1;" : "=f"(y) : "f"(x));
    return y;
}
__device__ __forceinline__ float4 to_tf32_4(float4 v) {
    v.x = to_tf32(v.x); v.y = to_tf32(v.y); v.z = to_tf32(v.z); v.w = to_tf32(v.w);
    return v;
}

__device__ __forceinline__ void mma_tf32(float* c, const uint32_t* a, uint32_t b0, uint32_t b1) {
    asm volatile(
        "mma.sync.aligned.m16n8k8.row.col.f32.tf32.tf32.f32 "
        "{%0,%1,%2,%3}, {%4,%5,%6,%7}, {%8,%9}, {%0,%1,%2,%3};\n"
        : "+f"(c[0]), "+f"(c[1]), "+f"(c[2]), "+f"(c[3])
        : "r"(a[0]), "r"(a[1]), "r"(a[2]), "r"(a[3]), "r"(b0), "r"(b1));
}

// ---------------- zero output + counters ----------------
__global__ void zero_kernel(float* __restrict__ y) {
    size_t i = (size_t)blockIdx.x * blockDim.x + threadIdx.x;
    size_t n4 = (size_t)TT * HH / 4;
    if (i < n4) {
        float4 z = {0.f, 0.f, 0.f, 0.f};
        reinterpret_cast<float4*>(y)[i] = z;
    }
    if (blockIdx.x == 0 && threadIdx.x < EE) g_cnt[threadIdx.x] = 0;
}

// ---------------- router ----------------
__global__ void __launch_bounds__(512) router_kernel(
    const float* __restrict__ x, const float* __restrict__ wr,
    const float* __restrict__ br, float* __restrict__ scores) {
    int t = blockIdx.x;
    int lane = threadIdx.x & 31;
    int e = threadIdx.x >> 5;

    const float* xr = x + (size_t)t * HH;
    const float* w  = wr + (size_t)e * HH;
    float s = 0.f;
    for (int i = lane; i < HH; i += 32) s += xr[i] * w[i];
    #pragma unroll
    for (int o = 16; o > 0; o >>= 1) s += __shfl_xor_sync(0xffffffffu, s, o);

    __shared__ float logit[EE];
    if (lane == 0) logit[e] = s + br[e];
    __syncthreads();

    if (threadIdx.x == 0) {
        float v[EE];
        #pragma unroll
        for (int i = 0; i < EE; i++) v[i] = logit[i];
        int bi[KTOP]; float bv[KTOP];
        #pragma unroll
        for (int k = 0; k < KTOP; k++) {
            float best = -1e30f; int b = 0;
            #pragma unroll
            for (int i = 0; i < EE; i++)
                if (v[i] > best) { best = v[i]; b = i; }
            bv[k] = best; bi[k] = b; v[b] = -1e30f;
        }
        float m = bv[0];
        float ex[KTOP], sum = 0.f;
        #pragma unroll
        for (int k = 0; k < KTOP; k++) { ex[k] = __expf(bv[k] - m); sum += ex[k]; }
        float inv = 1.f / sum;
        #pragma unroll
        for (int k = 0; k < KTOP; k++) {
            float sc = ex[k] * inv;
            if (scores) scores[t * KTOP + k] = sc * 0.25f;
            int pos = atomicAdd(&g_cnt[bi[k]], 1);
            g_rows[bi[k] * TT + pos] = t;
            g_wt[bi[k] * TT + pos]  = sc;
        }
    }
}

// ---------------- GEMM1 (tf32 mma): gathered x @ Wgu -> fused GLU ----------
// BM=128, BN=64 gate + 64 up (paired), BK=16. 8 warps, warp tile 32x32.
__global__ void __launch_bounds__(256) gemm1_kernel(
    const float* __restrict__ x, const float* __restrict__ wgu,
    const float* __restrict__ bgu) {
    int e = blockIdx.z;
    int cnt = g_cnt[e];
    int m0 = blockIdx.y * 128;
    if (m0 >= cnt) return;
    int n0 = blockIdx.x * 64;

    __shared__ __align__(16) float As[2][128][20];
    __shared__ __align__(16) float Bg[2][16][72];
    __shared__ __align__(16) float Bu[2][16][72];
    __shared__ int tok[128];

    int tid = threadIdx.x;
    if (tid < 128) {
        int r = m0 + tid;
        tok[tid] = (r < cnt) ? g_rows[e * TT + r] : -1;
    }
    __syncthreads();

    int lane = tid & 31, wid = tid >> 5;
    int wm = wid & 3, wn = wid >> 2;
    int gid = lane >> 2, qt = lane & 3;

    // global A: two rows per thread
    int amr = tid >> 2;            // 0..63
    int ak4 = (tid & 3) * 4;
    int t0 = tok[amr], t1 = tok[amr + 64];
    const float* ap0 = (t0 >= 0) ? x + (size_t)t0 * HH + ak4 : nullptr;
    const float* ap1 = (t1 >= 0) ? x + (size_t)t1 * HH + ak4 : nullptr;
    // global B: one row of gate + one of up per thread
    int bk = tid >> 4;             // 0..15
    int bn4 = (tid & 15) * 4;
    const float* bp = wgu + (size_t)e * HH * (2 * DD) + (size_t)bk * (2 * DD) + n0 + bn4;

    float accg[2][4][4] = {}, accu[2][4][4] = {};
    float4 ra0, ra1, rbg, rbu;

    // prefetch chunk 0
    {
        float4 z = {0.f,0.f,0.f,0.f};
        ra0 = ap0 ? *(const float4*)(ap0) : z;
        ra1 = ap1 ? *(const float4*)(ap1) : z;
        rbg = *(const float4*)(bp);
        rbu = *(const float4*)(bp + DD);
        *(float4*)&As[0][amr][ak4]      = to_tf32_4(ra0);
        *(float4*)&As[0][amr + 64][ak4] = to_tf32_4(ra1);
        *(float4*)&Bg[0][bk][bn4] = to_tf32_4(rbg);
        *(float4*)&Bu[0][bk][bn4] = to_tf32_4(rbu);
    }
    __syncthreads();

    for (int k0 = 0; k0 < HH; k0 += 16) {
        int buf = (k0 >> 4) & 1;
        bool more = (k0 + 16 < HH);
        if (more) {
            float4 z = {0.f,0.f,0.f,0.f};
            ra0 = ap0 ? *(const float4*)(ap0 + k0 + 16) : z;
            ra1 = ap1 ? *(const float4*)(ap1 + k0 + 16) : z;
            const float* b = bp + (size_t)(k0 + 16) * (2 * DD);
            rbg = *(const float4*)(b);
            rbu = *(const float4*)(b + DD);
        }
        #pragma unroll
        for (int ks = 0; ks < 2; ks++) {
            int kk = ks * 8 + qt;
            uint32_t a[2][4];
            #pragma unroll
            for (int mt = 0; mt < 2; mt++) {
                int r = wm * 32 + mt * 16 + gid;
                a[mt][0] = __float_as_uint(As[buf][r][kk]);
                a[mt][1] = __float_as_uint(As[buf][r + 8][kk]);
                a[mt][2] = __float_as_uint(As[buf][r][kk + 4]);
                a[mt][3] = __float_as_uint(As[buf][r + 8][kk + 4]);
            }
            #pragma unroll
            for (int nt = 0; nt < 4; nt++) {
                int n = wn * 32 + nt * 8 + gid;
                uint32_t g0 = __float_as_uint(Bg[buf][kk][n]);
                uint32_t g1 = __float_as_uint(Bg[buf][kk + 4][n]);
                uint32_t u0 = __float_as_uint(Bu[buf][kk][n]);
                uint32_t u1 = __float_as_uint(Bu[buf][kk + 4][n]);
                #pragma unroll
                for (int mt = 0; mt < 2; mt++) {
                    mma_tf32(accg[mt][nt], a[mt], g0, g1);
                    mma_tf32(accu[mt][nt], a[mt], u0, u1);
                }
            }
        }
        if (more) {
            *(float4*)&As[buf ^ 1][amr][ak4]      = to_tf32_4(ra0);
            *(float4*)&As[buf ^ 1][amr + 64][ak4] = to_tf32_4(ra1);
            *(float4*)&Bg[buf ^ 1][bk][bn4] = to_tf32_4(rbg);
            *(float4*)&Bu[buf ^ 1][bk][bn4] = to_tf32_4(rbu);
        }
        __syncthreads();
    }

    const float* bgp = bgu + (size_t)e * (2 * DD);
    #pragma unroll
    for (int mt = 0; mt < 2; mt++) {
        #pragma unroll
        for (int i = 0; i < 2; i++) {
            int row = wm * 32 + mt * 16 + gid + i * 8;
            float* orow = g_gated + ((size_t)e * TT + m0 + row) * DD + n0;
            #pragma unroll
            for (int nt = 0; nt < 4; nt++) {
                int col = wn * 32 + nt * 8 + 2 * qt;
                #pragma unroll
                for (int j = 0; j < 2; j++) {
                    float gate = accg[mt][nt][i * 2 + j] + bgp[n0 + col + j];
                    float up   = accu[mt][nt][i * 2 + j] + bgp[DD + n0 + col + j];
                    gate = fminf(gate, LIMIT_C);
                    up   = fminf(fmaxf(up, -LIMIT_C), LIMIT_C);
                    float glu = gate / (1.f + __expf(-ALPHA_C * gate));
                    orow[col + j] = (up + 1.f) * glu;
                }
            }
        }
    }
}

// ---------------- GEMM2 (tf32 mma): gated @ Wd -> weighted scatter-add -----
// BM=128, BN=128, BK=16. 8 warps, warp tile 32x64.
__global__ void __launch_bounds__(256) gemm2_kernel(
    const float* __restrict__ dp, const float* __restrict__ bd,
    float* __restrict__ y) {
    int e = blockIdx.z;
    int cnt = g_cnt[e];
    int m0 = blockIdx.y * 128;
    if (m0 >= cnt) return;
    int n0 = blockIdx.x * 128;

    __shared__ __align__(16) float As[2][128][20];
    __shared__ __align__(16) float Bs[2][16][136];
    __shared__ int   tok[128];
    __shared__ float wts[128];

    int tid = threadIdx.x;
    if (tid < 128) {
        int r = m0 + tid;
        if (r < cnt) { tok[tid] = g_rows[e * TT + r]; wts[tid] = g_wt[e * TT + r]; }
        else         { tok[tid] = -1; wts[tid] = 0.f; }
    }
    __syncthreads();

    int lane = tid & 31, wid = tid >> 5;
    int wm = wid & 3, wn = wid >> 2;
    int gid = lane >> 2, qt = lane & 3;

    int amr = tid >> 2;
    int ak4 = (tid & 3) * 4;
    const float* ap0 = g_gated + ((size_t)e * TT + m0 + amr) * DD + ak4;
    const float* ap1 = ap0 + (size_t)64 * DD;

    int bk = tid >> 5;             // 0..7 (second row at +8)
    int bn4 = (tid & 31) * 4;
    const float* bp = dp + (size_t)e * DD * HH + (size_t)bk * HH + n0 + bn4;

    float acc[2][8][4] = {};
    float4 ra0, ra1, rb0, rb1;

    {
        ra0 = *(const float4*)(ap0);
        ra1 = *(const float4*)(ap1);
        rb0 = *(const float4*)(bp);
        rb1 = *(const float4*)(bp + (size_t)8 * HH);
        *(float4*)&As[0][amr][ak4]      = to_tf32_4(ra0);
        *(float4*)&As[0][amr + 64][ak4] = to_tf32_4(ra1);
        *(float4*)&Bs[0][bk][bn4]     = to_tf32_4(rb0);
        *(float4*)&Bs[0][bk + 8][bn4] = to_tf32_4(rb1);
    }
    __syncthreads();

    for (int k0 = 0; k0 < DD; k0 += 16) {
        int buf = (k0 >> 4) & 1;
        bool more = (k0 + 16 < DD);
        if (more) {
            ra0 = *(const float4*)(ap0 + k0 + 16);
            ra1 = *(const float4*)(ap1 + k0 + 16);
            const float* b = bp + (size_t)(k0 + 16) * HH;
            rb0 = *(const float4*)(b);
            rb1 = *(const float4*)(b + (size_t)8 * HH);
        }
        #pragma unroll
        for (int ks = 0; ks < 2; ks++) {
            int kk = ks * 8 + qt;
            uint32_t a[2][4];
            #pragma unroll
            for (int mt = 0; mt < 2; mt++) {
                int r = wm * 32 + mt * 16 + gid;
                a[mt][0] = __float_as_uint(As[buf][r][kk]);
                a[mt][1] = __float_as_uint(As[buf][r + 8][kk]);
                a[mt][2] = __float_as_uint(As[buf][r][kk + 4]);
                a[mt][3] = __float_as_uint(As[buf][r + 8][kk + 4]);
            }
            #pragma unroll
            for (int nt = 0; nt < 8; nt++) {
                int n = wn * 64 + nt * 8 + gid;
                uint32_t b0 = __float_as_uint(Bs[buf][kk][n]);
                uint32_t b1 = __float_as_uint(Bs[buf][kk + 4][n]);
                #pragma unroll
                for (int mt = 0; mt < 2; mt++)
                    mma_tf32(acc[mt][nt], a[mt], b0, b1);
            }
        }
        if (more) {
            *(float4*)&As[buf ^ 1][amr][ak4]      = to_tf32_4(ra0);
            *(float4*)&As[buf ^ 1][amr + 64][ak4] = to_tf32_4(ra1);
            *(float4*)&Bs[buf ^ 1][bk][bn4]     = to_tf32_4(rb0);
            *(float4*)&Bs[buf ^ 1][bk + 8][bn4] = to_tf32_4(rb1);
        }
        __syncthreads();
    }

    const float* bdp = bd + (size_t)e * HH;
    #pragma unroll
    for (int mt = 0; mt < 2; mt++) {
        #pragma unroll
        for (int i = 0; i < 2; i++) {
            int row = wm * 32 + mt * 16 + gid + i * 8;
            if (m0 + row < cnt) {
                float wv = wts[row];
                int t = tok[row];
                float* yrow = y + (size_t)t * HH + n0;
                #pragma unroll
                for (int nt = 0; nt < 8; nt++) {
                    int col = wn * 64 + nt * 8 + 2 * qt;
                    #pragma unroll
                    for (int j = 0; j < 2; j++) {
                        float out = (acc[mt][nt][i * 2 + j] + bdp[n0 + col + j]) * wv;
                        atomicAdd(yrow + col + j, out);
                    }
                }
            }
        }
    }
}

// ---------------- launch ----------------
extern "C" void kernel_launch(void* const* d_in, const int* in_sizes, int n_in,
                              void* d_out, int out_size) {
    const float* x   = (const float*)d_in[0];
    const float* wr  = (const float*)d_in[1];
    const float* br  = (const float*)d_in[2];
    const float* wgu = (const float*)d_in[3];
    const float* bgu = (const float*)d_in[4];
    const float* dp  = (const float*)d_in[5];
    const float* bd  = (const float*)d_in[6];
    (void)in_sizes; (void)n_in;

    float* y = (float*)d_out;
    float* scores = nullptr;
    if ((size_t)out_size >= (size_t)TT * HH + (size_t)TT * KTOP)
        scores = y + (size_t)TT * HH;

    {
        int threads = 256;
        int blocks = (int)(((size_t)TT * HH / 4 + threads - 1) / threads);
        zero_kernel<<<blocks, threads>>>(y);
    }
    router_kernel<<<TT, 512>>>(x, wr, br, scores);

    dim3 g1(DD / 64, TT / 128, EE);
    gemm1_kernel<<<g1, 256>>>(x, wgu, bgu);

    dim3 g2(HH / 128, TT / 128, EE);
    gemm2_kernel<<<g2, 256>>>(dp, bd, y);
}

// round 3
// speedup vs baseline: 3.3928x; 1.0009x over previous
#include <cuda_runtime.h>
#include <cstdint>

// Problem constants
#define TT 4096      // tokens = B*S
#define HH 2048      // hidden
#define DD 2048      // intermediate (gate_up = 2*DD)
#define EE 16
#define KTOP 4
#define ALPHA_C 1.702f
#define LIMIT_C 7.0f

// ---------------- device scratch ----------------
__device__ int   g_cnt[EE];
__device__ int   g_rows[EE * TT];
__device__ float g_wt[EE * TT];
__device__ float g_gated[(size_t)EE * TT * DD];

__device__ __forceinline__ float to_tf32(float x) {
    float y;
    asm("cvt.rna.tf32.f32 %0, %1;" : "=f"(y) : "f"(x));
    return y;
}
__device__ __forceinline__ float4 to_tf32_4(float4 v) {
    v.x = to_tf32(v.x); v.y = to_tf32(v.y); v.z = to_tf32(v.z); v.w = to_tf32(v.w);
    return v;
}

__device__ __forceinline__ void mma_tf32(float* c, const uint32_t* a, uint32_t b0, uint32_t b1) {
    asm volatile(
        "mma.sync.aligned.m16n8k8.row.col.f32.tf32.tf32.f32 "
        "{%0,%1,%2,%3}, {%4,%5,%6,%7}, {%8,%9}, {%0,%1,%2,%3};\n"
        : "+f"(c[0]), "+f"(c[1]), "+f"(c[2]), "+f"(c[3])
        : "r"(a[0]), "r"(a[1]), "r"(a[2]), "r"(a[3]), "r"(b0), "r"(b1));
}

// ---------------- zero output + counters ----------------
__global__ void zero_kernel(float* __restrict__ y) {
    size_t i = (size_t)blockIdx.x * blockDim.x + threadIdx.x;
    size_t n4 = (size_t)TT * HH / 4;
    if (i < n4) {
        float4 z = {0.f, 0.f, 0.f, 0.f};
        reinterpret_cast<float4*>(y)[i] = z;
    }
    if (blockIdx.x == 0 && threadIdx.x < EE) g_cnt[threadIdx.x] = 0;
}

// ---------------- router ----------------
__global__ void __launch_bounds__(512) router_kernel(
    const float* __restrict__ x, const float* __restrict__ wr,
    const float* __restrict__ br, float* __restrict__ scores) {
    int t = blockIdx.x;
    int lane = threadIdx.x & 31;
    int e = threadIdx.x >> 5;

    const float* xr = x + (size_t)t * HH;
    const float* w  = wr + (size_t)e * HH;
    float s = 0.f;
    for (int i = lane; i < HH; i += 32) s += xr[i] * w[i];
    #pragma unroll
    for (int o = 16; o > 0; o >>= 1) s += __shfl_xor_sync(0xffffffffu, s, o);

    __shared__ float logit[EE];
    if (lane == 0) logit[e] = s + br[e];
    __syncthreads();

    if (threadIdx.x == 0) {
        float v[EE];
        #pragma unroll
        for (int i = 0; i < EE; i++) v[i] = logit[i];
        int bi[KTOP]; float bv[KTOP];
        #pragma unroll
        for (int k = 0; k < KTOP; k++) {
            float best = -1e30f; int b = 0;
            #pragma unroll
            for (int i = 0; i < EE; i++)
                if (v[i] > best) { best = v[i]; b = i; }
            bv[k] = best; bi[k] = b; v[b] = -1e30f;
        }
        float m = bv[0];
        float ex[KTOP], sum = 0.f;
        #pragma unroll
        for (int k = 0; k < KTOP; k++) { ex[k] = __expf(bv[k] - m); sum += ex[k]; }
        float inv = 1.f / sum;
        #pragma unroll
        for (int k = 0; k < KTOP; k++) {
            float sc = ex[k] * inv;
            if (scores) scores[t * KTOP + k] = sc * 0.25f;
            int pos = atomicAdd(&g_cnt[bi[k]], 1);
            g_rows[bi[k] * TT + pos] = t;
            g_wt[bi[k] * TT + pos]  = sc;
        }
    }
}

// ---------------- GEMM1 (tf32 mma): gathered x @ Wgu -> fused GLU ----------
// BM=128, BN=64 gate + 64 up (paired), BK=16. 8 warps, warp tile 32x32.
__global__ void __launch_bounds__(256) gemm1_kernel(
    const float* __restrict__ x, const float* __restrict__ wgu,
    const float* __restrict__ bgu) {
    int e = blockIdx.z;
    int cnt = g_cnt[e];
    int m0 = blockIdx.y * 128;
    if (m0 >= cnt) return;
    int n0 = blockIdx.x * 64;

    __shared__ __align__(16) float As[2][128][20];
    __shared__ __align__(16) float Bg[2][16][72];
    __shared__ __align__(16) float Bu[2][16][72];
    __shared__ int tok[128];

    int tid = threadIdx.x;
    if (tid < 128) {
        int r = m0 + tid;
        tok[tid] = (r < cnt) ? g_rows[e * TT + r] : -1;
    }
    __syncthreads();

    int lane = tid & 31, wid = tid >> 5;
    int wm = wid & 3, wn = wid >> 2;
    int gid = lane >> 2, qt = lane & 3;

    // global A: two rows per thread
    int amr = tid >> 2;            // 0..63
    int ak4 = (tid & 3) * 4;
    int t0 = tok[amr], t1 = tok[amr + 64];
    const float* ap0 = (t0 >= 0) ? x + (size_t)t0 * HH + ak4 : nullptr;
    const float* ap1 = (t1 >= 0) ? x + (size_t)t1 * HH + ak4 : nullptr;
    // global B: one row of gate + one of up per thread
    int bk = tid >> 4;             // 0..15
    int bn4 = (tid & 15) * 4;
    const float* bp = wgu + (size_t)e * HH * (2 * DD) + (size_t)bk * (2 * DD) + n0 + bn4;

    float accg[2][4][4] = {}, accu[2][4][4] = {};
    float4 ra0, ra1, rbg, rbu;

    // prefetch chunk 0
    {
        float4 z = {0.f,0.f,0.f,0.f};
        ra0 = ap0 ? *(const float4*)(ap0) : z;
        ra1 = ap1 ? *(const float4*)(ap1) : z;
        rbg = *(const float4*)(bp);
        rbu = *(const float4*)(bp + DD);
        *(float4*)&As[0][amr][ak4]      = to_tf32_4(ra0);
        *(float4*)&As[0][amr + 64][ak4] = to_tf32_4(ra1);
        *(float4*)&Bg[0][bk][bn4] = to_tf32_4(rbg);
        *(float4*)&Bu[0][bk][bn4] = to_tf32_4(rbu);
    }
    __syncthreads();

    for (int k0 = 0; k0 < HH; k0 += 16) {
        int buf = (k0 >> 4) & 1;
        bool more = (k0 + 16 < HH);
        if (more) {
            float4 z = {0.f,0.f,0.f,0.f};
            ra0 = ap0 ? *(const float4*)(ap0 + k0 + 16) : z;
            ra1 = ap1 ? *(const float4*)(ap1 + k0 + 16) : z;
            const float* b = bp + (size_t)(k0 + 16) * (2 * DD);
            rbg = *(const float4*)(b);
            rbu = *(const float4*)(b + DD);
        }
        #pragma unroll
        for (int ks = 0; ks < 2; ks++) {
            int kk = ks * 8 + qt;
            uint32_t a[2][4];
            #pragma unroll
            for (int mt = 0; mt < 2; mt++) {
                int r = wm * 32 + mt * 16 + gid;
                a[mt][0] = __float_as_uint(As[buf][r][kk]);
                a[mt][1] = __float_as_uint(As[buf][r + 8][kk]);
                a[mt][2] = __float_as_uint(As[buf][r][kk + 4]);
                a[mt][3] = __float_as_uint(As[buf][r + 8][kk + 4]);
            }
            #pragma unroll
            for (int nt = 0; nt < 4; nt++) {
                int n = wn * 32 + nt * 8 + gid;
                uint32_t g0 = __float_as_uint(Bg[buf][kk][n]);
                uint32_t g1 = __float_as_uint(Bg[buf][kk + 4][n]);
                uint32_t u0 = __float_as_uint(Bu[buf][kk][n]);
                uint32_t u1 = __float_as_uint(Bu[buf][kk + 4][n]);
                #pragma unroll
                for (int mt = 0; mt < 2; mt++) {
                    mma_tf32(accg[mt][nt], a[mt], g0, g1);
                    mma_tf32(accu[mt][nt], a[mt], u0, u1);
                }
            }
        }
        if (more) {
            *(float4*)&As[buf ^ 1][amr][ak4]      = to_tf32_4(ra0);
            *(float4*)&As[buf ^ 1][amr + 64][ak4] = to_tf32_4(ra1);
            *(float4*)&Bg[buf ^ 1][bk][bn4] = to_tf32_4(rbg);
            *(float4*)&Bu[buf ^ 1][bk][bn4] = to_tf32_4(rbu);
        }
        __syncthreads();
    }

    const float* bgp = bgu + (size_t)e * (2 * DD);
    #pragma unroll
    for (int mt = 0; mt < 2; mt++) {
        #pragma unroll
        for (int i = 0; i < 2; i++) {
            int row = wm * 32 + mt * 16 + gid + i * 8;
            float* orow = g_gated + ((size_t)e * TT + m0 + row) * DD + n0;
            #pragma unroll
            for (int nt = 0; nt < 4; nt++) {
                int col = wn * 32 + nt * 8 + 2 * qt;
                #pragma unroll
                for (int j = 0; j < 2; j++) {
                    float gate = accg[mt][nt][i * 2 + j] + bgp[n0 + col + j];
                    float up   = accu[mt][nt][i * 2 + j] + bgp[DD + n0 + col + j];
                    gate = fminf(gate, LIMIT_C);
                    up   = fminf(fmaxf(up, -LIMIT_C), LIMIT_C);
                    float glu = gate / (1.f + __expf(-ALPHA_C * gate));
                    orow[col + j] = (up + 1.f) * glu;
                }
            }
        }
    }
}

// ---------------- GEMM2 (tf32 mma): gated @ Wd -> weighted scatter-add -----
// BM=128, BN=128, BK=16. 8 warps, warp tile 32x64.
__global__ void __launch_bounds__(256) gemm2_kernel(
    const float* __restrict__ dp, const float* __restrict__ bd,
    float* __restrict__ y) {
    int e = blockIdx.z;
    int cnt = g_cnt[e];
    int m0 = blockIdx.y * 128;
    if (m0 >= cnt) return;
    int n0 = blockIdx.x * 128;

    __shared__ __align__(16) float As[2][128][20];
    __shared__ __align__(16) float Bs[2][16][136];
    __shared__ int   tok[128];
    __shared__ float wts[128];

    int tid = threadIdx.x;
    if (tid < 128) {
        int r = m0 + tid;
        if (r < cnt) { tok[tid] = g_rows[e * TT + r]; wts[tid] = g_wt[e * TT + r]; }
        else         { tok[tid] = -1; wts[tid] = 0.f; }
    }
    __syncthreads();

    int lane = tid & 31, wid = tid >> 5;
    int wm = wid & 3, wn = wid >> 2;
    int gid = lane >> 2, qt = lane & 3;

    int amr = tid >> 2;
    int ak4 = (tid & 3) * 4;
    const float* ap0 = g_gated + ((size_t)e * TT + m0 + amr) * DD + ak4;
    const float* ap1 = ap0 + (size_t)64 * DD;

    int bk = tid >> 5;             // 0..7 (second row at +8)
    int bn4 = (tid & 31) * 4;
    const float* bp = dp + (size_t)e * DD * HH + (size_t)bk * HH + n0 + bn4;

    float acc[2][8][4] = {};
    float4 ra0, ra1, rb0, rb1;

    {
        ra0 = *(const float4*)(ap0);
        ra1 = *(const float4*)(ap1);
        rb0 = *(const float4*)(bp);
        rb1 = *(const float4*)(bp + (size_t)8 * HH);
        *(float4*)&As[0][amr][ak4]      = to_tf32_4(ra0);
        *(float4*)&As[0][amr + 64][ak4] = to_tf32_4(ra1);
        *(float4*)&Bs[0][bk][bn4]     = to_tf32_4(rb0);
        *(float4*)&Bs[0][bk + 8][bn4] = to_tf32_4(rb1);
    }
    __syncthreads();

    for (int k0 = 0; k0 < DD; k0 += 16) {
        int buf = (k0 >> 4) & 1;
        bool more = (k0 + 16 < DD);
        if (more) {
            ra0 = *(const float4*)(ap0 + k0 + 16);
            ra1 = *(const float4*)(ap1 + k0 + 16);
            const float* b = bp + (size_t)(k0 + 16) * HH;
            rb0 = *(const float4*)(b);
            rb1 = *(const float4*)(b + (size_t)8 * HH);
        }
        #pragma unroll
        for (int ks = 0; ks < 2; ks++) {
            int kk = ks * 8 + qt;
            uint32_t a[2][4];
            #pragma unroll
            for (int mt = 0; mt < 2; mt++) {
                int r = wm * 32 + mt * 16 + gid;
                a[mt][0] = __float_as_uint(As[buf][r][kk]);
                a[mt][1] = __float_as_uint(As[buf][r + 8][kk]);
                a[mt][2] = __float_as_uint(As[buf][r][kk + 4]);
                a[mt][3] = __float_as_uint(As[buf][r + 8][kk + 4]);
            }
            #pragma unroll
            for (int nt = 0; nt < 8; nt++) {
                int n = wn * 64 + nt * 8 + gid;
                uint32_t b0 = __float_as_uint(Bs[buf][kk][n]);
                uint32_t b1 = __float_as_uint(Bs[buf][kk + 4][n]);
                #pragma unroll
                for (int mt = 0; mt < 2; mt++)
                    mma_tf32(acc[mt][nt], a[mt], b0, b1);
            }
        }
        if (more) {
            *(float4*)&As[buf ^ 1][amr][ak4]      = to_tf32_4(ra0);
            *(float4*)&As[buf ^ 1][amr + 64][ak4] = to_tf32_4(ra1);
            *(float4*)&Bs[buf ^ 1][bk][bn4]     = to_tf32_4(rb0);
            *(float4*)&Bs[buf ^ 1][bk + 8][bn4] = to_tf32_4(rb1);
        }
        __syncthreads();
    }

    const float* bdp = bd + (size_t)e * HH;
    #pragma unroll
    for (int mt = 0; mt < 2; mt++) {
        #pragma unroll
        for (int i = 0; i < 2; i++) {
            int row = wm * 32 + mt * 16 + gid + i * 8;
            if (m0 + row < cnt) {
                float wv = wts[row];
                int t = tok[row];
                float* yrow = y + (size_t)t * HH + n0;
                #pragma unroll
                for (int nt = 0; nt < 8; nt++) {
                    int col = wn * 64 + nt * 8 + 2 * qt;
                    #pragma unroll
                    for (int j = 0; j < 2; j++) {
                        float out = (acc[mt][nt][i * 2 + j] + bdp[n0 + col + j]) * wv;
                        atomicAdd(yrow + col + j, out);
                    }
                }
            }
        }
    }
}

// ---------------- launch ----------------
extern "C" void kernel_launch(void* const* d_in, const int* in_sizes, int n_in,
                              void* d_out, int out_size) {
    const float* x   = (const float*)d_in[0];
    const float* wr  = (const float*)d_in[1];
    const float* br  = (const float*)d_in[2];
    const float* wgu = (const float*)d_in[3];
    const float* bgu = (const float*)d_in[4];
    const float* dp  = (const float*)d_in[5];
    const float* bd  = (const float*)d_in[6];
    (void)in_sizes; (void)n_in;

    float* y = (float*)d_out;
    float* scores = nullptr;
    if ((size_t)out_size >= (size_t)TT * HH + (size_t)TT * KTOP)
        scores = y + (size_t)TT * HH;

    {
        int threads = 256;
        int blocks = (int)(((size_t)TT * HH / 4 + threads - 1) / threads);
        zero_kernel<<<blocks, threads>>>(y);
    }
    router_kernel<<<TT, 512>>>(x, wr, br, scores);

    dim3 g1(DD / 64, TT / 128, EE);
    gemm1_kernel<<<g1, 256>>>(x, wgu, bgu);

    dim3 g2(HH / 128, TT / 128, EE);
    gemm2_kernel<<<g2, 256>>>(dp, bd, y);
}

// round 5
// speedup vs baseline: 7.0104x; 2.0662x over previous
#include <cuda_runtime.h>
#include <cuda_fp16.h>
#include <cstdint>

#define TT 4096
#define HH 2048
#define DD 2048
#define EE 16
#define KTOP 4
#define ALPHA_C 1.702f
#define LIMIT_C 7.0f
#define BK 32
#define NC (HH / BK)     // 64 (HH == DD)

// ---------------- device scratch ----------------
__device__ int    g_cnt[EE];
__device__ int    g_rows[EE * TT];
__device__ int    g_slotk[TT * KTOP];
__device__ float  g_wk4[TT * KTOP];
__device__ __half g_xh[(size_t)TT * HH];
__device__ __half g_wguH[(size_t)EE * HH * (2 * DD)];
__device__ __half g_dpH[(size_t)EE * DD * HH];
__device__ __half g_gatedH[(size_t)EE * TT * DD];
__device__ float  g_out2[(size_t)EE * TT * HH];

// ---------------- helpers ----------------
__device__ __forceinline__ uint32_t smem_u32(const void* p) {
    uint32_t a;
    asm("{ .reg .u64 t; cvta.to.shared.u64 t, %1; cvt.u32.u64 %0, t; }" : "=r"(a) : "l"(p));
    return a;
}
__device__ __forceinline__ void ldsm4(uint32_t* r, uint32_t addr) {
    asm volatile("ldmatrix.sync.aligned.m8n8.x4.shared.b16 {%0,%1,%2,%3}, [%4];"
        : "=r"(r[0]), "=r"(r[1]), "=r"(r[2]), "=r"(r[3]) : "r"(addr));
}
__device__ __forceinline__ void ldsm2t(uint32_t& r0, uint32_t& r1, uint32_t addr) {
    asm volatile("ldmatrix.sync.aligned.m8n8.x2.trans.shared.b16 {%0,%1}, [%2];"
        : "=r"(r0), "=r"(r1) : "r"(addr));
}
__device__ __forceinline__ void mma16816(float* c, const uint32_t* a, uint32_t b0, uint32_t b1) {
    asm volatile("mma.sync.aligned.m16n8k16.row.col.f32.f16.f16.f32 "
        "{%0,%1,%2,%3}, {%4,%5,%6,%7}, {%8,%9}, {%0,%1,%2,%3};"
        : "+f"(c[0]), "+f"(c[1]), "+f"(c[2]), "+f"(c[3])
        : "r"(a[0]), "r"(a[1]), "r"(a[2]), "r"(a[3]), "r"(b0), "r"(b1));
}
__device__ __forceinline__ void cpa16(uint32_t dst, const void* src) {
    asm volatile("cp.async.cg.shared.global [%0], [%1], 16;" :: "r"(dst), "l"(src));
}
__device__ __forceinline__ void cpa16z(uint32_t dst, const void* src, int sz) {
    asm volatile("cp.async.cg.shared.global [%0], [%1], 16, %2;" :: "r"(dst), "l"(src), "r"(sz));
}
__device__ __forceinline__ void cpa_commit() {
    asm volatile("cp.async.commit_group;" ::: "memory");
}
template <int N>
__device__ __forceinline__ void cpa_wait() {
    asm volatile("cp.async.wait_group %0;" :: "n"(N) : "memory");
}

// ---------------- small kernels ----------------
__global__ void init_kernel() {
    if (threadIdx.x < EE) g_cnt[threadIdx.x] = 0;
}

__global__ void cvt_kernel(const float* __restrict__ s, __half* __restrict__ d, size_t n4) {
    size_t i = (size_t)blockIdx.x * blockDim.x + threadIdx.x;
    if (i < n4) {
        float4 v = reinterpret_cast<const float4*>(s)[i];
        __half2 h0 = __floats2half2_rn(v.x, v.y);
        __half2 h1 = __floats2half2_rn(v.z, v.w);
        reinterpret_cast<__half2*>(d)[2 * i]     = h0;
        reinterpret_cast<__half2*>(d)[2 * i + 1] = h1;
    }
}

// ---------------- router ----------------
__global__ void __launch_bounds__(512) router_kernel(
    const float* __restrict__ x, const float* __restrict__ wr,
    const float* __restrict__ br, float* __restrict__ scores) {
    int t = blockIdx.x;
    int lane = threadIdx.x & 31;
    int e = threadIdx.x >> 5;

    const float* xr = x + (size_t)t * HH;
    const float* w  = wr + (size_t)e * HH;
    float s = 0.f;
    for (int i = lane; i < HH; i += 32) s += xr[i] * w[i];
    #pragma unroll
    for (int o = 16; o > 0; o >>= 1) s += __shfl_xor_sync(0xffffffffu, s, o);

    __shared__ float logit[EE];
    if (lane == 0) logit[e] = s + br[e];
    __syncthreads();

    if (threadIdx.x == 0) {
        float v[EE];
        #pragma unroll
        for (int i = 0; i < EE; i++) v[i] = logit[i];
        int bi[KTOP]; float bv[KTOP];
        #pragma unroll
        for (int k = 0; k < KTOP; k++) {
            float best = -1e30f; int b = 0;
            #pragma unroll
            for (int i = 0; i < EE; i++)
                if (v[i] > best) { best = v[i]; b = i; }
            bv[k] = best; bi[k] = b; v[b] = -1e30f;
        }
        float m = bv[0];
        float ex[KTOP], sum = 0.f;
        #pragma unroll
        for (int k = 0; k < KTOP; k++) { ex[k] = __expf(bv[k] - m); sum += ex[k]; }
        float inv = 1.f / sum;
        #pragma unroll
        for (int k = 0; k < KTOP; k++) {
            float sc = ex[k] * inv;
            if (scores) scores[t * KTOP + k] = sc * 0.25f;
            int pos = atomicAdd(&g_cnt[bi[k]], 1);
            g_rows[bi[k] * TT + pos] = t;
            g_slotk[t * KTOP + k] = bi[k] * TT + pos;
            g_wk4[t * KTOP + k]  = sc;
        }
    }
}

// ---------------- GEMM1: fp16 mma, gathered x @ Wgu -> fused GLU -----------
// BM=128, BN=64 (gate) + 64 (up), BK=32; 8 warps as 2(m)x4(n), warp 64x16.
__global__ void __launch_bounds__(256) gemm1_kernel(const float* __restrict__ bgu) {
    int e = blockIdx.z;
    int cnt = g_cnt[e];
    int m0 = blockIdx.y * 128;
    if (m0 >= cnt) return;
    int n0 = blockIdx.x * 64;

    // A: 128 rows x 40 halfs (80B pitch -> conflict-free LDSM via 20*m mod 32)
    __shared__ __align__(16) __half sA[2][128 * 40];
    __shared__ __align__(16) __half sBg[2][32 * 64];    // [k][n], chunk-XOR swizzled
    __shared__ __align__(16) __half sBu[2][32 * 64];
    __shared__ int tok[128];

    int tid = threadIdx.x, lane = tid & 31, wid = tid >> 5;
    if (tid < 128) {
        int r = m0 + tid;
        tok[tid] = (r < cnt) ? g_rows[e * TT + r] : -1;
    }
    __syncthreads();

    uint32_t aB[2] = { smem_u32(sA[0]),  smem_u32(sA[1])  };
    uint32_t gBf[2] = { smem_u32(sBg[0]), smem_u32(sBg[1]) };
    uint32_t uBf[2] = { smem_u32(sBu[0]), smem_u32(sBu[1]) };

    // A: 512 chunks (128 rows x 4 x 16B) -> 2/thread
    const __half* srcA[2]; uint32_t dstA[2]; int szA[2];
    #pragma unroll
    for (int i = 0; i < 2; i++) {
        int q = tid + i * 256, row = q >> 2, c4 = q & 3;
        int t = tok[row];
        szA[i] = (t >= 0) ? 16 : 0;
        if (t < 0) t = 0;
        srcA[i] = g_xh + (size_t)t * HH + c4 * 8;
        dstA[i] = (uint32_t)(row * 80 + c4 * 16);
    }
    // B: 256 chunks each (32 rows x 8 x 16B) -> 1 gate + 1 up per thread
    int bk_ = tid >> 3, bc = tid & 7;
    uint32_t dstB = (uint32_t)(bk_ * 128 + ((bc ^ (bk_ & 7)) << 4));
    const __half* srcBg = g_wguH + ((size_t)e * HH + bk_) * (2 * DD) + n0 + bc * 8;
    const __half* srcBu = srcBg + DD;

    int wm = wid >> 2, wn = wid & 3;      // 2 x 4
    float accg[4][2][4] = {}, accu[4][2][4] = {};

    // per-lane LDSM address components
    uint32_t aRow = (uint32_t)((lane & 15) * 80 + (lane >> 4) * 16);
    int kl = lane & 15, klx = kl & 7;
    uint32_t bRow = (uint32_t)(kl * 128);

    // prologue
    {
        #pragma unroll
        for (int i = 0; i < 2; i++) cpa16z(aB[0] + dstA[i], srcA[i], szA[i]);
        cpa16(gBf[0] + dstB, srcBg);
        cpa16(uBf[0] + dstB, srcBu);
        cpa_commit();
    }

    for (int c = 0; c < NC; c++) {
        int b = c & 1;
        if (c + 1 < NC) {
            #pragma unroll
            for (int i = 0; i < 2; i++)
                cpa16z(aB[b ^ 1] + dstA[i], srcA[i] + (size_t)(c + 1) * BK, szA[i]);
            cpa16(gBf[b ^ 1] + dstB, srcBg + (size_t)(c + 1) * BK * (2 * DD));
            cpa16(uBf[b ^ 1] + dstB, srcBu + (size_t)(c + 1) * BK * (2 * DD));
            cpa_commit();
            cpa_wait<1>();
        } else {
            cpa_wait<0>();
        }
        __syncthreads();

        #pragma unroll
        for (int ks = 0; ks < 2; ks++) {
            uint32_t a[4][4];
            #pragma unroll
            for (int mt = 0; mt < 4; mt++)
                ldsm4(a[mt], aB[b] + (uint32_t)((wm * 64 + mt * 16) * 80 + ks * 32) + aRow);
            #pragma unroll
            for (int nt = 0; nt < 2; nt++) {
                int cn = wn * 2 + nt;
                uint32_t sw = (uint32_t)(((cn ^ klx) << 4) + ks * 2048) + bRow;
                uint32_t bg0, bg1, bu0, bu1;
                ldsm2t(bg0, bg1, gBf[b] + sw);
                ldsm2t(bu0, bu1, uBf[b] + sw);
                #pragma unroll
                for (int mt = 0; mt < 4; mt++) {
                    mma16816(accg[mt][nt], a[mt], bg0, bg1);
                    mma16816(accu[mt][nt], a[mt], bu0, bu1);
                }
            }
        }
        __syncthreads();
    }

    // epilogue: fused GLU -> g_gatedH (fp16)
    int gid = lane >> 2, qt = lane & 3;
    const float* bgp = bgu + (size_t)e * (2 * DD) + n0;
    #pragma unroll
    for (int mt = 0; mt < 4; mt++) {
        #pragma unroll
        for (int i = 0; i < 2; i++) {
            int row = m0 + wm * 64 + mt * 16 + gid + i * 8;
            __half* orow = g_gatedH + ((size_t)e * TT + row) * DD + n0;
            #pragma unroll
            for (int nt = 0; nt < 2; nt++) {
                int col = wn * 16 + nt * 8 + 2 * qt;
                float g0 = accg[mt][nt][i * 2 + 0] + bgp[col];
                float g1 = accg[mt][nt][i * 2 + 1] + bgp[col + 1];
                float u0 = accu[mt][nt][i * 2 + 0] + bgp[DD + col];
                float u1 = accu[mt][nt][i * 2 + 1] + bgp[DD + col + 1];
                g0 = fminf(g0, LIMIT_C); g1 = fminf(g1, LIMIT_C);
                u0 = fminf(fmaxf(u0, -LIMIT_C), LIMIT_C);
                u1 = fminf(fmaxf(u1, -LIMIT_C), LIMIT_C);
                float o0 = (u0 + 1.f) * (g0 / (1.f + __expf(-ALPHA_C * g0)));
                float o1 = (u1 + 1.f) * (g1 / (1.f + __expf(-ALPHA_C * g1)));
                *reinterpret_cast<__half2*>(orow + col) = __floats2half2_rn(o0, o1);
            }
        }
    }
}

// ---------------- GEMM2: fp16 mma, gated @ Wd -> per-slot out2 -------------
// BM=128, BN=128, BK=32; 8 warps as 2(m)x4(n), warp 64x32.
__global__ void __launch_bounds__(256) gemm2_kernel() {
    int e = blockIdx.z;
    int cnt = g_cnt[e];
    int m0 = blockIdx.y * 128;
    if (m0 >= cnt) return;
    int n0 = blockIdx.x * 128;

    __shared__ __align__(16) __half sA[2][128 * 40];
    __shared__ __align__(16) __half sB[2][32 * 128];   // [k][n], 256B rows, swizzled

    int tid = threadIdx.x, lane = tid & 31, wid = tid >> 5;

    uint32_t aB[2] = { smem_u32(sA[0]), smem_u32(sA[1]) };
    uint32_t bB[2] = { smem_u32(sB[0]), smem_u32(sB[1]) };

    const __half* srcA[2]; uint32_t dstA[2];
    #pragma unroll
    for (int i = 0; i < 2; i++) {
        int q = tid + i * 256, row = q >> 2, c4 = q & 3;
        srcA[i] = g_gatedH + ((size_t)e * TT + m0 + row) * DD + c4 * 8;
        dstA[i] = (uint32_t)(row * 80 + c4 * 16);
    }
    const __half* srcB[2]; uint32_t dstB[2];
    #pragma unroll
    for (int i = 0; i < 2; i++) {
        int q = tid + i * 256, k = q >> 4, c = q & 15;
        srcB[i] = g_dpH + ((size_t)e * DD + k) * HH + n0 + c * 8;
        dstB[i] = (uint32_t)(k * 256 + ((c ^ (k & 7)) << 4));
    }

    int wm = wid >> 2, wn = wid & 3;
    float acc[4][4][4] = {};

    uint32_t aRow = (uint32_t)((lane & 15) * 80 + (lane >> 4) * 16);
    int kl = lane & 15, klx = kl & 7;
    uint32_t bRow = (uint32_t)(kl * 256);

    {
        #pragma unroll
        for (int i = 0; i < 2; i++) cpa16(aB[0] + dstA[i], srcA[i]);
        #pragma unroll
        for (int i = 0; i < 2; i++) cpa16(bB[0] + dstB[i], srcB[i]);
        cpa_commit();
    }

    for (int c = 0; c < NC; c++) {
        int b = c & 1;
        if (c + 1 < NC) {
            #pragma unroll
            for (int i = 0; i < 2; i++)
                cpa16(aB[b ^ 1] + dstA[i], srcA[i] + (size_t)(c + 1) * BK);
            #pragma unroll
            for (int i = 0; i < 2; i++)
                cpa16(bB[b ^ 1] + dstB[i], srcB[i] + (size_t)(c + 1) * BK * HH);
            cpa_commit();
            cpa_wait<1>();
        } else {
            cpa_wait<0>();
        }
        __syncthreads();

        #pragma unroll
        for (int ks = 0; ks < 2; ks++) {
            uint32_t a[4][4];
            #pragma unroll
            for (int mt = 0; mt < 4; mt++)
                ldsm4(a[mt], aB[b] + (uint32_t)((wm * 64 + mt * 16) * 80 + ks * 32) + aRow);
            #pragma unroll
            for (int nt = 0; nt < 4; nt++) {
                int cn = wn * 4 + nt;
                uint32_t sw = (uint32_t)(((cn ^ klx) << 4) + ks * 4096) + bRow;
                uint32_t b0, b1;
                ldsm2t(b0, b1, bB[b] + sw);
                #pragma unroll
                for (int mt = 0; mt < 4; mt++)
                    mma16816(acc[mt][nt], a[mt], b0, b1);
            }
        }
        __syncthreads();
    }

    int gid = lane >> 2, qt = lane & 3;
    #pragma unroll
    for (int mt = 0; mt < 4; mt++) {
        #pragma unroll
        for (int i = 0; i < 2; i++) {
            int srow = m0 + wm * 64 + mt * 16 + gid + i * 8;
            if (srow < cnt) {
                float* orow = g_out2 + ((size_t)e * TT + srow) * HH + n0;
                #pragma unroll
                for (int nt = 0; nt < 4; nt++) {
                    int col = wn * 32 + nt * 8 + 2 * qt;
                    float2 o = make_float2(acc[mt][nt][i * 2], acc[mt][nt][i * 2 + 1]);
                    *reinterpret_cast<float2*>(orow + col) = o;
                }
            }
        }
    }
}

// ---------------- combine: y[t] = sum_k w_k * (out2_k + bias_k) ------------
__global__ void __launch_bounds__(256) combine_kernel(
    const float* __restrict__ bd, float* __restrict__ y) {
    int t = blockIdx.x, tid = threadIdx.x;
    __shared__ int sl[KTOP];
    __shared__ float sw[KTOP];
    if (tid < KTOP) { sl[tid] = g_slotk[t * KTOP + tid]; sw[tid] = g_wk4[t * KTOP + tid]; }
    __syncthreads();
    #pragma unroll
    for (int i = 0; i < 2; i++) {
        int h = (tid + i * 256) * 4;
        float4 acc = {0.f, 0.f, 0.f, 0.f};
        #pragma unroll
        for (int k = 0; k < KTOP; k++) {
            int s = sl[k];
            float w = sw[k];
            float4 o = *reinterpret_cast<const float4*>(g_out2 + (size_t)s * HH + h);
            float4 b = *reinterpret_cast<const float4*>(bd + (size_t)(s >> 12) * HH + h);
            acc.x += w * (o.x + b.x);
            acc.y += w * (o.y + b.y);
            acc.z += w * (o.z + b.z);
            acc.w += w * (o.w + b.w);
        }
        *reinterpret_cast<float4*>(y + (size_t)t * HH + h) = acc;
    }
}

// ---------------- launch ----------------
extern "C" void kernel_launch(void* const* d_in, const int* in_sizes, int n_in,
                              void* d_out, int out_size) {
    const float* x   = (const float*)d_in[0];
    const float* wr  = (const float*)d_in[1];
    const float* br  = (const float*)d_in[2];
    const float* wgu = (const float*)d_in[3];
    const float* bgu = (const float*)d_in[4];
    const float* dp  = (const float*)d_in[5];
    const float* bd  = (const float*)d_in[6];
    (void)in_sizes; (void)n_in;

    float* y = (float*)d_out;
    float* scores = nullptr;
    if ((size_t)out_size >= (size_t)TT * HH + (size_t)TT * KTOP)
        scores = y + (size_t)TT * HH;

    init_kernel<<<1, 32>>>();

    __half* xh;   cudaGetSymbolAddress((void**)&xh,   g_xh);
    __half* wguH; cudaGetSymbolAddress((void**)&wguH, g_wguH);
    __half* dpH;  cudaGetSymbolAddress((void**)&dpH,  g_dpH);

    {
        size_t n4 = (size_t)TT * HH / 4;
        cvt_kernel<<<(int)((n4 + 255) / 256), 256>>>(x, xh, n4);
        n4 = (size_t)EE * HH * (2 * DD) / 4;
        cvt_kernel<<<(int)((n4 + 255) / 256), 256>>>(wgu, wguH, n4);
        n4 = (size_t)EE * DD * HH / 4;
        cvt_kernel<<<(int)((n4 + 255) / 256), 256>>>(dp, dpH, n4);
    }

    router_kernel<<<TT, 512>>>(x, wr, br, scores);

    dim3 g1(DD / 64, TT / 128, EE);
    gemm1_kernel<<<g1, 256>>>(bgu);

    dim3 g2(HH / 128, TT / 128, EE);
    gemm2_kernel<<<g2, 256>>>();

    combine_kernel<<<TT, 256>>>(bd, y);
}

// round 6
// speedup vs baseline: 7.9037x; 1.1274x over previous
#include <cuda_runtime.h>
#include <cuda_fp16.h>
#include <cstdint>

#define TT 4096
#define HH 2048
#define DD 2048
#define EE 16
#define KTOP 4
#define ALPHA_C 1.702f
#define LIMIT_C 7.0f
#define BK 32
#define NC (HH / BK)     // 64 (HH == DD)

// GEMM1 dynamic smem: A 4*10240, Bg 4*4096, Bu 4*4096, tok 512
#define G1_A_OFF   0
#define G1_BG_OFF  (4 * 10240)
#define G1_BU_OFF  (G1_BG_OFF + 4 * 4096)
#define G1_TOK_OFF (G1_BU_OFF + 4 * 4096)
#define G1_SMEM    (G1_TOK_OFF + 512)
// GEMM2 dynamic smem: A 4*10240, B 4*8192
#define G2_A_OFF   0
#define G2_B_OFF   (4 * 10240)
#define G2_SMEM    (G2_B_OFF + 4 * 8192)

// ---------------- device scratch ----------------
__device__ int    g_cnt[EE];
__device__ int    g_rows[EE * TT];
__device__ int    g_slotk[TT * KTOP];
__device__ float  g_wk4[TT * KTOP];
__device__ __half g_xh[(size_t)TT * HH];
__device__ __half g_wguH[(size_t)EE * HH * (2 * DD)];
__device__ __half g_dpH[(size_t)EE * DD * HH];
__device__ __half g_gatedH[(size_t)EE * TT * DD];
__device__ __half g_out2h[(size_t)EE * TT * HH];

// ---------------- helpers ----------------
__device__ __forceinline__ uint32_t smem_u32(const void* p) {
    uint32_t a;
    asm("{ .reg .u64 t; cvta.to.shared.u64 t, %1; cvt.u32.u64 %0, t; }" : "=r"(a) : "l"(p));
    return a;
}
__device__ __forceinline__ void ldsm4(uint32_t* r, uint32_t addr) {
    asm volatile("ldmatrix.sync.aligned.m8n8.x4.shared.b16 {%0,%1,%2,%3}, [%4];"
        : "=r"(r[0]), "=r"(r[1]), "=r"(r[2]), "=r"(r[3]) : "r"(addr));
}
__device__ __forceinline__ void ldsm2t(uint32_t& r0, uint32_t& r1, uint32_t addr) {
    asm volatile("ldmatrix.sync.aligned.m8n8.x2.trans.shared.b16 {%0,%1}, [%2];"
        : "=r"(r0), "=r"(r1) : "r"(addr));
}
__device__ __forceinline__ void mma16816(float* c, const uint32_t* a, uint32_t b0, uint32_t b1) {
    asm volatile("mma.sync.aligned.m16n8k16.row.col.f32.f16.f16.f32 "
        "{%0,%1,%2,%3}, {%4,%5,%6,%7}, {%8,%9}, {%0,%1,%2,%3};"
        : "+f"(c[0]), "+f"(c[1]), "+f"(c[2]), "+f"(c[3])
        : "r"(a[0]), "r"(a[1]), "r"(a[2]), "r"(a[3]), "r"(b0), "r"(b1));
}
__device__ __forceinline__ void cpa16(uint32_t dst, const void* src) {
    asm volatile("cp.async.cg.shared.global [%0], [%1], 16;" :: "r"(dst), "l"(src));
}
__device__ __forceinline__ void cpa16z(uint32_t dst, const void* src, int sz) {
    asm volatile("cp.async.cg.shared.global [%0], [%1], 16, %2;" :: "r"(dst), "l"(src), "r"(sz));
}
__device__ __forceinline__ void cpa_commit() {
    asm volatile("cp.async.commit_group;" ::: "memory");
}
template <int N>
__device__ __forceinline__ void cpa_wait() {
    asm volatile("cp.async.wait_group %0;" :: "n"(N) : "memory");
}
__device__ __forceinline__ void pipe_wait(int c) {
    if (c + 2 < NC)      cpa_wait<2>();
    else if (c + 1 < NC) cpa_wait<1>();
    else                 cpa_wait<0>();
}

// ---------------- small kernels ----------------
__global__ void init_kernel() {
    if (threadIdx.x < EE) g_cnt[threadIdx.x] = 0;
}

__global__ void cvt_kernel(const float* __restrict__ s, __half* __restrict__ d, size_t n4) {
    size_t i = (size_t)blockIdx.x * blockDim.x + threadIdx.x;
    if (i < n4) {
        float4 v = reinterpret_cast<const float4*>(s)[i];
        __half2 h0 = __floats2half2_rn(v.x, v.y);
        __half2 h1 = __floats2half2_rn(v.z, v.w);
        reinterpret_cast<__half2*>(d)[2 * i]     = h0;
        reinterpret_cast<__half2*>(d)[2 * i + 1] = h1;
    }
}

// ---------------- router ----------------
__global__ void __launch_bounds__(512) router_kernel(
    const float* __restrict__ x, const float* __restrict__ wr,
    const float* __restrict__ br, float* __restrict__ scores) {
    int t = blockIdx.x;
    int lane = threadIdx.x & 31;
    int e = threadIdx.x >> 5;

    const float* xr = x + (size_t)t * HH;
    const float* w  = wr + (size_t)e * HH;
    float s = 0.f;
    for (int i = lane; i < HH; i += 32) s += xr[i] * w[i];
    #pragma unroll
    for (int o = 16; o > 0; o >>= 1) s += __shfl_xor_sync(0xffffffffu, s, o);

    __shared__ float logit[EE];
    if (lane == 0) logit[e] = s + br[e];
    __syncthreads();

    if (threadIdx.x == 0) {
        float v[EE];
        #pragma unroll
        for (int i = 0; i < EE; i++) v[i] = logit[i];
        int bi[KTOP]; float bv[KTOP];
        #pragma unroll
        for (int k = 0; k < KTOP; k++) {
            float best = -1e30f; int b = 0;
            #pragma unroll
            for (int i = 0; i < EE; i++)
                if (v[i] > best) { best = v[i]; b = i; }
            bv[k] = best; bi[k] = b; v[b] = -1e30f;
        }
        float m = bv[0];
        float ex[KTOP], sum = 0.f;
        #pragma unroll
        for (int k = 0; k < KTOP; k++) { ex[k] = __expf(bv[k] - m); sum += ex[k]; }
        float inv = 1.f / sum;
        #pragma unroll
        for (int k = 0; k < KTOP; k++) {
            float sc = ex[k] * inv;
            if (scores) scores[t * KTOP + k] = sc * 0.25f;
            int pos = atomicAdd(&g_cnt[bi[k]], 1);
            g_rows[bi[k] * TT + pos] = t;
            g_slotk[t * KTOP + k] = bi[k] * TT + pos;
            g_wk4[t * KTOP + k]  = sc;
        }
    }
}

// ---------------- GEMM1: fp16 mma, gathered x @ Wgu -> fused GLU -----------
// BM=128, BN=64 gate + 64 up, BK=32; 8 warps 2(m)x4(n); 4-stage cp.async.
__global__ void __launch_bounds__(256, 2) gemm1_kernel(const float* __restrict__ bgu) {
    int e = blockIdx.z;
    int cnt = g_cnt[e];
    int m0 = blockIdx.y * 128;
    if (m0 >= cnt) return;
    int n0 = blockIdx.x * 64;

    extern __shared__ __align__(16) char dyn[];
    uint32_t aBase = smem_u32(dyn + G1_A_OFF);
    uint32_t gBase = smem_u32(dyn + G1_BG_OFF);
    uint32_t uBase = smem_u32(dyn + G1_BU_OFF);
    int* tok = (int*)(dyn + G1_TOK_OFF);

    int tid = threadIdx.x, lane = tid & 31, wid = tid >> 5;
    if (tid < 128) {
        int r = m0 + tid;
        tok[tid] = (r < cnt) ? g_rows[e * TT + r] : -1;
    }
    __syncthreads();

    // A: 512 16B-chunks/stage -> 2/thread  (row pitch 80B, conflict-free LDSM)
    const __half* srcA[2]; uint32_t dstA[2]; int szA[2];
    #pragma unroll
    for (int i = 0; i < 2; i++) {
        int q = tid + i * 256, row = q >> 2, c4 = q & 3;
        int t = tok[row];
        szA[i] = (t >= 0) ? 16 : 0;
        if (t < 0) t = 0;
        srcA[i] = g_xh + (size_t)t * HH + c4 * 8;
        dstA[i] = aBase + (uint32_t)(row * 80 + c4 * 16);
    }
    // B: [k][n] 128B rows, chunk-XOR swizzle; 1 gate + 1 up chunk/thread
    int bk_ = tid >> 3, bc = tid & 7;
    uint32_t dstB = (uint32_t)(bk_ * 128 + ((bc ^ (bk_ & 7)) << 4));
    const __half* srcBg = g_wguH + ((size_t)e * HH + bk_) * (2 * DD) + n0 + bc * 8;
    const __half* srcBu = srcBg + DD;

    int wm = wid >> 2, wn = wid & 3;
    float accg[4][2][4] = {}, accu[4][2][4] = {};

    uint32_t aRow = (uint32_t)((lane & 15) * 80 + (lane >> 4) * 16);
    int kl = lane & 15, klx = kl & 7;
    uint32_t bRow = (uint32_t)(kl * 128);

    // prologue: stages 0..2
    #pragma unroll
    for (int s = 0; s < 3; s++) {
        #pragma unroll
        for (int i = 0; i < 2; i++)
            cpa16z(dstA[i] + s * 10240, srcA[i] + (size_t)s * BK, szA[i]);
        cpa16(gBase + s * 4096 + dstB, srcBg + (size_t)s * BK * (2 * DD));
        cpa16(uBase + s * 4096 + dstB, srcBu + (size_t)s * BK * (2 * DD));
        cpa_commit();
    }

    for (int c = 0; c < NC; c++) {
        pipe_wait(c);
        __syncthreads();
        int buf = c & 3;
        uint32_t aS = aBase + buf * 10240;
        uint32_t gS = gBase + buf * 4096;
        uint32_t uS = uBase + buf * 4096;

        #pragma unroll
        for (int ks = 0; ks < 2; ks++) {
            uint32_t a[4][4];
            #pragma unroll
            for (int mt = 0; mt < 4; mt++)
                ldsm4(a[mt], aS + (uint32_t)((wm * 64 + mt * 16) * 80 + ks * 32) + aRow);
            #pragma unroll
            for (int nt = 0; nt < 2; nt++) {
                int cn = wn * 2 + nt;
                uint32_t sw = (uint32_t)(((cn ^ klx) << 4) + ks * 2048) + bRow;
                uint32_t bg0, bg1, bu0, bu1;
                ldsm2t(bg0, bg1, gS + sw);
                ldsm2t(bu0, bu1, uS + sw);
                #pragma unroll
                for (int mt = 0; mt < 4; mt++) {
                    mma16816(accg[mt][nt], a[mt], bg0, bg1);
                    mma16816(accu[mt][nt], a[mt], bu0, bu1);
                }
            }
        }

        int nc_ = c + 3;
        if (nc_ < NC) {
            int s = nc_ & 3;
            #pragma unroll
            for (int i = 0; i < 2; i++)
                cpa16z(dstA[i] + s * 10240, srcA[i] + (size_t)nc_ * BK, szA[i]);
            cpa16(gBase + s * 4096 + dstB, srcBg + (size_t)nc_ * BK * (2 * DD));
            cpa16(uBase + s * 4096 + dstB, srcBu + (size_t)nc_ * BK * (2 * DD));
            cpa_commit();
        }
    }

    // epilogue: fused GLU -> g_gatedH (fp16)
    int gid = lane >> 2, qt = lane & 3;
    const float* bgp = bgu + (size_t)e * (2 * DD) + n0;
    #pragma unroll
    for (int mt = 0; mt < 4; mt++) {
        #pragma unroll
        for (int i = 0; i < 2; i++) {
            int row = m0 + wm * 64 + mt * 16 + gid + i * 8;
            __half* orow = g_gatedH + ((size_t)e * TT + row) * DD + n0;
            #pragma unroll
            for (int nt = 0; nt < 2; nt++) {
                int col = wn * 16 + nt * 8 + 2 * qt;
                float g0 = accg[mt][nt][i * 2 + 0] + bgp[col];
                float g1 = accg[mt][nt][i * 2 + 1] + bgp[col + 1];
                float u0 = accu[mt][nt][i * 2 + 0] + bgp[DD + col];
                float u1 = accu[mt][nt][i * 2 + 1] + bgp[DD + col + 1];
                g0 = fminf(g0, LIMIT_C); g1 = fminf(g1, LIMIT_C);
                u0 = fminf(fmaxf(u0, -LIMIT_C), LIMIT_C);
                u1 = fminf(fmaxf(u1, -LIMIT_C), LIMIT_C);
                float o0 = (u0 + 1.f) * (g0 / (1.f + __expf(-ALPHA_C * g0)));
                float o1 = (u1 + 1.f) * (g1 / (1.f + __expf(-ALPHA_C * g1)));
                *reinterpret_cast<__half2*>(orow + col) = __floats2half2_rn(o0, o1);
            }
        }
    }
}

// ---------------- GEMM2: fp16 mma, gated @ Wd -> per-slot out2 (fp16) ------
// BM=128, BN=128, BK=32; 8 warps 2(m)x4(n); 4-stage cp.async.
__global__ void __launch_bounds__(256, 2) gemm2_kernel() {
    int e = blockIdx.z;
    int cnt = g_cnt[e];
    int m0 = blockIdx.y * 128;
    if (m0 >= cnt) return;
    int n0 = blockIdx.x * 128;

    extern __shared__ __align__(16) char dyn[];
    uint32_t aBase = smem_u32(dyn + G2_A_OFF);
    uint32_t bBase = smem_u32(dyn + G2_B_OFF);

    int tid = threadIdx.x, lane = tid & 31, wid = tid >> 5;

    const __half* srcA[2]; uint32_t dstA[2];
    #pragma unroll
    for (int i = 0; i < 2; i++) {
        int q = tid + i * 256, row = q >> 2, c4 = q & 3;
        srcA[i] = g_gatedH + ((size_t)e * TT + m0 + row) * DD + c4 * 8;
        dstA[i] = aBase + (uint32_t)(row * 80 + c4 * 16);
    }
    const __half* srcB[2]; uint32_t dstB[2];
    #pragma unroll
    for (int i = 0; i < 2; i++) {
        int q = tid + i * 256, k = q >> 4, c = q & 15;
        srcB[i] = g_dpH + ((size_t)e * DD + k) * HH + n0 + c * 8;
        dstB[i] = bBase + (uint32_t)(k * 256 + ((c ^ (k & 7)) << 4));
    }

    int wm = wid >> 2, wn = wid & 3;
    float acc[4][4][4] = {};

    uint32_t aRow = (uint32_t)((lane & 15) * 80 + (lane >> 4) * 16);
    int kl = lane & 15, klx = kl & 7;
    uint32_t bRow = (uint32_t)(kl * 256);

    #pragma unroll
    for (int s = 0; s < 3; s++) {
        #pragma unroll
        for (int i = 0; i < 2; i++)
            cpa16(dstA[i] + s * 10240, srcA[i] + (size_t)s * BK);
        #pragma unroll
        for (int i = 0; i < 2; i++)
            cpa16(dstB[i] + s * 8192, srcB[i] + (size_t)s * BK * HH);
        cpa_commit();
    }

    for (int c = 0; c < NC; c++) {
        pipe_wait(c);
        __syncthreads();
        int buf = c & 3;
        uint32_t aS = aBase + buf * 10240;
        uint32_t bS = bBase + buf * 8192;

        #pragma unroll
        for (int ks = 0; ks < 2; ks++) {
            uint32_t a[4][4];
            #pragma unroll
            for (int mt = 0; mt < 4; mt++)
                ldsm4(a[mt], aS + (uint32_t)((wm * 64 + mt * 16) * 80 + ks * 32) + aRow);
            #pragma unroll
            for (int nt = 0; nt < 4; nt++) {
                int cn = wn * 4 + nt;
                uint32_t sw = (uint32_t)(((cn ^ klx) << 4) + ks * 4096) + bRow;
                uint32_t b0, b1;
                ldsm2t(b0, b1, bS + sw);
                #pragma unroll
                for (int mt = 0; mt < 4; mt++)
                    mma16816(acc[mt][nt], a[mt], b0, b1);
            }
        }

        int nc_ = c + 3;
        if (nc_ < NC) {
            int s = nc_ & 3;
            #pragma unroll
            for (int i = 0; i < 2; i++)
                cpa16(dstA[i] + s * 10240, srcA[i] + (size_t)nc_ * BK);
            #pragma unroll
            for (int i = 0; i < 2; i++)
                cpa16(dstB[i] + s * 8192, srcB[i] + (size_t)nc_ * BK * HH);
            cpa_commit();
        }
    }

    int gid = lane >> 2, qt = lane & 3;
    #pragma unroll
    for (int mt = 0; mt < 4; mt++) {
        #pragma unroll
        for (int i = 0; i < 2; i++) {
            int srow = m0 + wm * 64 + mt * 16 + gid + i * 8;
            if (srow < cnt) {
                __half* orow = g_out2h + ((size_t)e * TT + srow) * HH + n0;
                #pragma unroll
                for (int nt = 0; nt < 4; nt++) {
                    int col = wn * 32 + nt * 8 + 2 * qt;
                    *reinterpret_cast<__half2*>(orow + col) =
                        __floats2half2_rn(acc[mt][nt][i * 2], acc[mt][nt][i * 2 + 1]);
                }
            }
        }
    }
}

// ---------------- combine: y[t] = sum_k w_k * (out2_k + bias_k) ------------
__global__ void __launch_bounds__(256) combine_kernel(
    const float* __restrict__ bd, float* __restrict__ y) {
    int t = blockIdx.x, tid = threadIdx.x;
    __shared__ int sl[KTOP];
    __shared__ float sw[KTOP];
    if (tid < KTOP) { sl[tid] = g_slotk[t * KTOP + tid]; sw[tid] = g_wk4[t * KTOP + tid]; }
    __syncthreads();
    #pragma unroll
    for (int i = 0; i < 2; i++) {
        int h = (tid + i * 256) * 4;
        float4 acc = {0.f, 0.f, 0.f, 0.f};
        #pragma unroll
        for (int k = 0; k < KTOP; k++) {
            int s = sl[k];
            float w = sw[k];
            const __half2* op = reinterpret_cast<const __half2*>(g_out2h + (size_t)s * HH + h);
            float2 o0 = __half22float2(op[0]);
            float2 o1 = __half22float2(op[1]);
            float4 b = *reinterpret_cast<const float4*>(bd + (size_t)(s >> 12) * HH + h);
            acc.x += w * (o0.x + b.x);
            acc.y += w * (o0.y + b.y);
            acc.z += w * (o1.x + b.z);
            acc.w += w * (o1.y + b.w);
        }
        *reinterpret_cast<float4*>(y + (size_t)t * HH + h) = acc;
    }
}

// ---------------- launch ----------------
extern "C" void kernel_launch(void* const* d_in, const int* in_sizes, int n_in,
                              void* d_out, int out_size) {
    const float* x   = (const float*)d_in[0];
    const float* wr  = (const float*)d_in[1];
    const float* br  = (const float*)d_in[2];
    const float* wgu = (const float*)d_in[3];
    const float* bgu = (const float*)d_in[4];
    const float* dp  = (const float*)d_in[5];
    const float* bd  = (const float*)d_in[6];
    (void)in_sizes; (void)n_in;

    float* y = (float*)d_out;
    float* scores = nullptr;
    if ((size_t)out_size >= (size_t)TT * HH + (size_t)TT * KTOP)
        scores = y + (size_t)TT * HH;

    static bool attr_set = false;
    if (!attr_set) {
        cudaFuncSetAttribute(gemm1_kernel, cudaFuncAttributeMaxDynamicSharedMemorySize, G1_SMEM);
        cudaFuncSetAttribute(gemm2_kernel, cudaFuncAttributeMaxDynamicSharedMemorySize, G2_SMEM);
        attr_set = true;
    }

    init_kernel<<<1, 32>>>();

    __half* xh;   cudaGetSymbolAddress((void**)&xh,   g_xh);
    __half* wguH; cudaGetSymbolAddress((void**)&wguH, g_wguH);
    __half* dpH;  cudaGetSymbolAddress((void**)&dpH,  g_dpH);

    {
        size_t n4 = (size_t)TT * HH / 4;
        cvt_kernel<<<(int)((n4 + 255) / 256), 256>>>(x, xh, n4);
        n4 = (size_t)EE * HH * (2 * DD) / 4;
        cvt_kernel<<<(int)((n4 + 255) / 256), 256>>>(wgu, wguH, n4);
        n4 = (size_t)EE * DD * HH / 4;
        cvt_kernel<<<(int)((n4 + 255) / 256), 256>>>(dp, dpH, n4);
    }

    router_kernel<<<TT, 512>>>(x, wr, br, scores);

    dim3 g1(DD / 64, TT / 128, EE);
    gemm1_kernel<<<g1, 256, G1_SMEM>>>(bgu);

    dim3 g2(HH / 128, TT / 128, EE);
    gemm2_kernel<<<g2, 256, G2_SMEM>>>();

    combine_kernel<<<TT, 256>>>(bd, y);
}